// round 8
// baseline (speedup 1.0000x reference)
#include <cuda_runtime.h>
#include <cstdint>

#define T_STEPS 1024
#define NB 8192
#define NP 6
#define CHUNKS 32
#define CLEN (T_STEPS / CHUNKS)      // 32 steps per chunk
#define B1 8                         // scan batch (steps per pipeline stage)
#define NBT1 (T_STEPS / B1)          // 128 batches
#define STAGES 3                     // cp.async ring depth per warp
#define B2 4                         // consumer register batch
#define NBT2 (CLEN / B2)             // 8 batches per chunk
#define SCAN_BLOCKS 64               // 64 blocks x 128 thr = 8192 scan threads
#define P2_PER_CHUNK 64              // 8192 basins / 128 thr
#define TOTAL_BLOCKS (SCAN_BLOCKS + CHUNKS * P2_PER_CHUNK)   // 2112

// checkpoint scratch + per-chunk ready counters
__device__ float g_ck_snow[CHUNKS * NB];
__device__ float g_ck_soil[CHUNKS * NB];
__device__ int   g_cnt[CHUNKS];

struct Params {
    float Qmax, Df, Tmax, Tmin, Smax, invSmax, posf_l2, c0;
};

__device__ __forceinline__ float ex2_approx(float x)
{
    float y;
    asm("ex2.approx.ftz.f32 %0, %1;" : "=f"(y) : "f"(x));
    return y;
}

__device__ __forceinline__ Params load_params(const float* __restrict__ sp, int b)
{
    const float lo[NP] = {0.0f, 100.0f, 10.0f, 0.0f, 0.0f, -3.0f};
    const float hi[NP] = {0.1f, 1500.0f, 50.0f, 5.0f, 3.0f, 0.0f};
    float prm[NP];
#pragma unroll
    for (int i = 0; i < NP; i++) {
        float x = sp[b * NP + i];
        float s = 1.0f / (1.0f + __expf(-x));
        prm[i] = lo[i] + (hi[i] - lo[i]) * s;
    }
    Params q;
    q.Smax = prm[1]; q.Qmax = prm[2]; q.Df = prm[3];
    q.Tmax = prm[4]; q.Tmin = prm[5];
    q.invSmax = 1.0f / prm[1];
    const float negf_l2 = -prm[0] * 1.4426950408889634f;   // -f*log2(e)
    q.posf_l2 = -negf_l2;
    q.c0 = negf_l2 * prm[1];                                // -f*log2(e)*Smax
    return q;
}

// one EXP-HYDRO step (MUST stay bit-identical between producer and consumer)
__device__ __forceinline__ void hydro_step(const Params& q,
                                           float p, float tm, float pe,
                                           float& snow, float& soil,
                                           float fx[8])
{
    const float snowfall    = (tm < q.Tmin) ? p : 0.0f;
    const float rainfall    = p - snowfall;
    const float melt        = fminf(snow, q.Df * fmaxf(tm - q.Tmax, 0.0f));
    const float evap        = pe * fminf(soil * q.invSmax, 1.0f);
    // Qmax * exp(-f*max(Smax-soil,0)) == Qmax * 2^min(c0 + posf_l2*soil, 0)
    const float baseflow    = q.Qmax * ex2_approx(fminf(fmaf(q.posf_l2, soil, q.c0), 0.0f));
    const float surfaceflow = fmaxf(soil - q.Smax, 0.0f);

    const float d_snow = snowfall - melt;
    const float d_soil = rainfall + melt - evap - baseflow - surfaceflow;

    snow = fmaxf(snow + d_snow, 1e-6f);
    soil = fmaxf(soil + d_soil, 1e-6f);

    fx[0] = snowfall; fx[1] = rainfall; fx[2] = melt; fx[3] = evap;
    fx[4] = baseflow; fx[5] = surfaceflow; fx[6] = d_snow; fx[7] = d_soil;
}

__device__ __forceinline__ void cpasync16(unsigned int dst_smem, const float* src)
{
    asm volatile("cp.async.cg.shared.global [%0], [%1], 16;"
                 :: "r"(dst_smem), "l"(src));
}
__device__ __forceinline__ void cp_commit()
{
    asm volatile("cp.async.commit_group;" ::: "memory");
}
template <int N>
__device__ __forceinline__ void cp_wait()
{
    asm volatile("cp.async.wait_group %0;" :: "n"(N) : "memory");
}
__device__ __forceinline__ int ld_acq(const int* p)
{
    int v;
    asm volatile("ld.acquire.gpu.global.s32 %0, [%1];" : "=r"(v) : "l"(p) : "memory");
    return v;
}

__global__ void zero_cnt_kernel()
{
    if (threadIdx.x < CHUNKS) g_cnt[threadIdx.x] = 0;
}

// ---------------- fused: scan producers (bids 0..63) + flux consumers -------
__global__ void __launch_bounds__(128, 8)
hydro_fused(const float* __restrict__ prcp,
            const float* __restrict__ temp,
            const float* __restrict__ pet,
            const float* __restrict__ sp,
            float* __restrict__ out)
{
    // per-warp cp.async ring: 4 warps x 3 stages x 3 arrays x 8 steps x 32 lanes = 36 KB
    __shared__ float ring[4][STAGES][3][B1][32];

    const int bid = blockIdx.x;
    const int tid = threadIdx.x;

    if (bid < SCAN_BLOCKS) {
        // ================= producer: serial state scan =================
        const int w    = tid >> 5;
        const int lane = tid & 31;
        const int b    = bid * 128 + tid;
        const int wbase = bid * 128 + w * 32;          // warp's basin base
        const Params q = load_params(sp, b);

        const float* pp = prcp + b;
        const float* tp = temp + b;
        const float* ep = pet  + b;
        // vector-copy bases (warp-aligned, no lane offset)
        const float* vp0 = prcp + wbase;
        const float* vp1 = temp + wbase;
        const float* vp2 = pet  + wbase;

        // cooperative vectorized fill: 24 rows of 128B per batch -> 192 x 16B
        // lane l handles seg = l&7, rows (l>>3)+4j, j=0..5
        const int seg = lane & 7;
        const int r0  = lane >> 3;
        auto issue = [&](int batch, int s) {
            const int bc = (batch < NBT1) ? batch : NBT1 - 1;
            const size_t tbase = (size_t)bc * B1 * NB;
#pragma unroll
            for (int j = 0; j < 6; j++) {
                const int row = r0 + 4 * j;            // 0..23
                const int a   = row >> 3;              // forcing array
                const int i   = row & 7;               // step within batch
                const float* src = (a == 0 ? vp0 : (a == 1 ? vp1 : vp2))
                                 + tbase + (size_t)i * NB + seg * 4;
                unsigned int dst = (unsigned int)__cvta_generic_to_shared(
                                       &ring[w][s][a][i][seg * 4]);
                cpasync16(dst, src);
            }
            cp_commit();
        };

#pragma unroll
        for (int s = 0; s < STAGES - 1; s++)
            issue(s, s);

        float snow = 0.0f, soil = 0.0f;
        float fx[8];

        for (int tb = 0; tb < NBT1; tb++) {
            issue(tb + STAGES - 1, (tb + STAGES - 1) % STAGES);
            cp_wait<STAGES - 1>();
            __syncwarp();

            if ((tb & 3) == 0) {
                const int c = tb >> 2;
                g_ck_snow[c * NB + b] = snow;
                g_ck_soil[c * NB + b] = soil;
                __threadfence();          // checkpoint visible device-wide
                __syncwarp();             // all lanes fenced before flag
                if (lane == 0) atomicAdd(&g_cnt[c], 1);
                if (c == CHUNKS - 1) {
                    cp_wait<0>();         // drain pending copies before exit
                    if (b < 0) g_ck_soil[b & 1] = fx[0] + fx[1] + fx[2] + fx[3]
                                                + fx[4] + fx[5] + fx[6] + fx[7];
                    return;
                }
            }

            const int s = tb % STAGES;
#pragma unroll
            for (int i = 0; i < B1; i++) {
                const float p  = ring[w][s][0][i][lane];
                const float tm = ring[w][s][1][i][lane];
                const float pe = ring[w][s][2][i][lane];
                hydro_step(q, p, tm, pe, snow, soil, fx);
            }
        }
        if (b < 0) g_ck_soil[b & 1] = fx[0] + fx[1] + fx[2] + fx[3]
                                    + fx[4] + fx[5] + fx[6] + fx[7];
    } else {
        // ================= consumer: recompute chunk, store fluxes =====
        const int idx = bid - SCAN_BLOCKS;
        const int c   = idx >> 6;            // chunk-major: early chunks first
        const int b   = (idx & 63) * 128 + tid;
        const Params q = load_params(sp, b);

        const size_t t0 = (size_t)c * CLEN;
        const float* pp = prcp + t0 * NB + b;
        const float* tp = temp + t0 * NB + b;
        const float* ep = pet  + t0 * NB + b;
        float*       o  = out  + t0 * (8 * NB) + b;

        float PA[B2], TA[B2], EA[B2];
        float PB[B2], TB[B2], EB[B2];
        float fx[8];

        // prefetch first batch BEFORE waiting (loads don't depend on checkpoint)
#pragma unroll
        for (int i = 0; i < B2; i++) {
            PA[i] = pp[i * NB]; TA[i] = tp[i * NB]; EA[i] = ep[i * NB];
        }

        // wait until all 256 scan warps published checkpoint c
        if (tid == 0) {
            while (ld_acq(&g_cnt[c]) < 256)
                __nanosleep(128);
        }
        __syncthreads();

        float snow = g_ck_snow[c * NB + b];
        float soil = g_ck_soil[c * NB + b];

        for (int tb = 0; tb < NBT2; tb += 2) {
            {
                const size_t base = (size_t)(tb + 1) * B2 * NB;
#pragma unroll
                for (int i = 0; i < B2; i++) {
                    PB[i] = pp[base + i * NB]; TB[i] = tp[base + i * NB]; EB[i] = ep[base + i * NB];
                }
            }
#pragma unroll
            for (int i = 0; i < B2; i++) {
                hydro_step(q, PA[i], TA[i], EA[i], snow, soil, fx);
                __stcs(o + 0 * NB, fx[0]); __stcs(o + 1 * NB, fx[1]);
                __stcs(o + 2 * NB, fx[2]); __stcs(o + 3 * NB, fx[3]);
                __stcs(o + 4 * NB, fx[4]); __stcs(o + 5 * NB, fx[5]);
                __stcs(o + 6 * NB, fx[6]); __stcs(o + 7 * NB, fx[7]);
                o += 8 * NB;
            }
            if (tb + 2 < NBT2) {
                const size_t base = (size_t)(tb + 2) * B2 * NB;
#pragma unroll
                for (int i = 0; i < B2; i++) {
                    PA[i] = pp[base + i * NB]; TA[i] = tp[base + i * NB]; EA[i] = ep[base + i * NB];
                }
            }
#pragma unroll
            for (int i = 0; i < B2; i++) {
                hydro_step(q, PB[i], TB[i], EB[i], snow, soil, fx);
                __stcs(o + 0 * NB, fx[0]); __stcs(o + 1 * NB, fx[1]);
                __stcs(o + 2 * NB, fx[2]); __stcs(o + 3 * NB, fx[3]);
                __stcs(o + 4 * NB, fx[4]); __stcs(o + 5 * NB, fx[5]);
                __stcs(o + 6 * NB, fx[6]); __stcs(o + 7 * NB, fx[7]);
                o += 8 * NB;
            }
        }
    }
}

extern "C" void kernel_launch(void* const* d_in, const int* in_sizes, int n_in,
                              void* d_out, int out_size)
{
    const float* prcp = (const float*)d_in[0];
    const float* temp = (const float*)d_in[1];
    const float* pet  = (const float*)d_in[2];
    const float* sp   = (const float*)d_in[3];
    float* out = (float*)d_out;

    zero_cnt_kernel<<<1, 32>>>();
    hydro_fused<<<TOTAL_BLOCKS, 128>>>(prcp, temp, pet, sp, out);
}